// round 15
// baseline (speedup 1.0000x reference)
#include <cuda_runtime.h>
#include <cuda_bf16.h>

// Problem shape (fixed by reference)
#define VOCAB   1000000
#define EMB     64
#define BATCH   4096
#define SLOTS   26
#define MAX_NNZ 10

static constexpr int PAIRS = BATCH * SLOTS;          // 106,496 (b,s) pairs
static constexpr int LANES_PER_PAIR = 16;            // 16 threads x float4 = 64 floats
static constexpr int THREADS = 512;

// CONVERGED CONFIG (R15). Measured landscape across 6 variants:
//  - every well-parallelized layout pins at ~5.1 TB/s HBM -> DRAM random-
//    access efficiency floor for ~472K scattered 256B granules. Traffic is
//    compulsory (121MB unique rows + 27MB out + 5MB keys ~= 153MB/replay).
//  - occupancy/MLP trades (R11), L2 evict_last pinning (R13: regressed warm
//    steady-state), 256-bit v8 loads at 8 lanes (R14: lost parallelism) all
//    failed to move the wall. R9's 16-lane 2x5-wave shape = measured optimum.
// This round: R9 structure + mask packed into one bitmask reg (frees ~9 regs
// of live state -> ptxas can keep more gathers in flight) + 512-thread blocks
// (half the CTAs, same warps).
__global__ __launch_bounds__(THREADS)
void emb_lookup_kernel(const int* __restrict__ keys,
                       const int* __restrict__ mask,
                       const float* __restrict__ table,
                       float* __restrict__ out)
{
    const int gid  = blockIdx.x * THREADS + threadIdx.x;
    const int pair = gid >> 4;          // (b*SLOTS + s)
    const int lane = gid & 15;          // which float4 of the 64-dim vector
    if (pair >= PAIRS) return;

    const int base = pair * MAX_NNZ;

    // Vectorized key/mask preload: 5x int2 each (40B per pair, 8B aligned).
    // Mask words collapse into a 10-bit register bitmask immediately.
    const int2* kp = reinterpret_cast<const int2*>(keys + base);
    const int2* mp = reinterpret_cast<const int2*>(mask + base);
    int k[MAX_NNZ];
    unsigned mbits = 0;
#pragma unroll
    for (int j = 0; j < 5; j++) {
        const int2 kk = kp[j];
        const int2 mv = mp[j];
        k[2*j]   = kk.x;  k[2*j+1] = kk.y;
        mbits |= (mv.x != 0 ? 1u : 0u) << (2*j);      // nonzero = valid
        mbits |= (mv.y != 0 ? 1u : 0u) << (2*j + 1);  // (i32 0/1 or f32 1.0 bits)
    }

    const int cnt = __popc(mbits);

    float4 acc = make_float4(0.f, 0.f, 0.f, 0.f);

    // Two waves of 5 batched, predicated gathers: zero-init + @P LDG.E.128
    // keeps 5 independent float4 loads in flight before any FADD consumes one.
#pragma unroll
    for (int w = 0; w < 2; w++) {
        float4 v[5];
#pragma unroll
        for (int j = 0; j < 5; j++) {
            const int n = w * 5 + j;
            v[j] = make_float4(0.f, 0.f, 0.f, 0.f);
            if (mbits & (1u << n)) {
                v[j] = *reinterpret_cast<const float4*>(
                    table + (size_t)k[n] * EMB + lane * 4);
            }
        }
#pragma unroll
        for (int j = 0; j < 5; j++) {
            acc.x += v[j].x; acc.y += v[j].y;
            acc.z += v[j].z; acc.w += v[j].w;
        }
    }

    const float inv = 1.0f / (float)(cnt > 0 ? cnt : 1);
    float4 r;
    r.x = acc.x * inv;
    r.y = acc.y * inv;
    r.z = acc.z * inv;
    r.w = acc.w * inv;

    // Streaming store: evict-first in L2, keep capacity for table lines.
    __stcs(reinterpret_cast<float4*>(out + (size_t)pair * EMB + lane * 4), r);
}

extern "C" void kernel_launch(void* const* d_in, const int* in_sizes, int n_in,
                              void* d_out, int out_size)
{
    const int*   keys  = (const int*)d_in[0];
    const int*   mask  = (const int*)d_in[1];
    const float* table = (const float*)d_in[2];
    float*       out   = (float*)d_out;

    const int total_threads = PAIRS * LANES_PER_PAIR;
    const int blocks = (total_threads + THREADS - 1) / THREADS;
    emb_lookup_kernel<<<blocks, THREADS>>>(keys, mask, table, out);
}

// round 16
// speedup vs baseline: 1.1627x; 1.1627x over previous
#include <cuda_runtime.h>
#include <cuda_bf16.h>

// Problem shape (fixed by reference)
#define VOCAB   1000000
#define EMB     64
#define BATCH   4096
#define SLOTS   26
#define MAX_NNZ 10

static constexpr int PAIRS = BATCH * SLOTS;          // 106,496 (b,s) pairs
static constexpr int LANES_PER_PAIR = 16;            // 16 threads x float4 = 64 floats
static constexpr int THREADS = 256;

// FINAL (R16) = R9 config, the measured optimum across 7 variants.
//
// One (batch,slot) pair per 16-thread group; each lane owns one float4 of the
// 64-dim vector, so a row gather is a fully coalesced 256B read (one LDG.E.128
// warp instruction covers 512B = two pairs' rows). Masked rows are never
// loaded (saves ~40% gather traffic at 60% density). Keys/mask read as int2
// vectors; output written with streaming stores.
//
// Measured landscape (bench us / kernel us / HBM GB/s):
//   R6  16-lane scalar keys        33.2 / 32.4 / 4757
//   R9  THIS SHAPE                 31.5 / 29.8 / 5099   <- optimum
//   R11 deep-MLP, launch_bounds 2  32.4 / 30.3 / 5054   (occ/MLP zero-sum)
//   R13 L2 evict_last pinning      35.6 / 29.3c/ 5171   (warm thrash regress)
//   R14 v8 256-bit, 8 lanes        35.3 / 32.9 / 4573   (lost parallelism)
//   R15 512-blk + bitmask          37.3 / 35.6 / 4298   (occupancy broke)
// Conclusion: pinned at the HBM random-access efficiency floor (~5.1 TB/s on
// ~472K scattered 256B granules). Compulsory traffic ~153MB -> ~30us kernel.
__global__ __launch_bounds__(THREADS)
void emb_lookup_kernel(const int* __restrict__ keys,
                       const int* __restrict__ mask,
                       const float* __restrict__ table,
                       float* __restrict__ out)
{
    const int gid  = blockIdx.x * THREADS + threadIdx.x;
    const int pair = gid >> 4;          // (b*SLOTS + s)
    const int lane = gid & 15;          // which float4 of the 64-dim vector
    if (pair >= PAIRS) return;

    const int base = pair * MAX_NNZ;

    // Vectorized key/mask preload: 5x int2 each (40B per pair, 8B aligned).
    const int2* kp = reinterpret_cast<const int2*>(keys + base);
    const int2* mp = reinterpret_cast<const int2*>(mask + base);
    int  k[MAX_NNZ];
    bool m[MAX_NNZ];
#pragma unroll
    for (int j = 0; j < 5; j++) {
        const int2 kk = kp[j];
        const int2 mm = mp[j];
        k[2*j]   = kk.x;  k[2*j+1] = kk.y;
        m[2*j]   = (mm.x != 0);          // works for int32 0/1 AND f32 0.0/1.0 bits
        m[2*j+1] = (mm.y != 0);
    }

    int cnt = 0;
#pragma unroll
    for (int n = 0; n < MAX_NNZ; n++) cnt += m[n] ? 1 : 0;

    float4 acc = make_float4(0.f, 0.f, 0.f, 0.f);

    // Two waves of 5 batched, predicated gathers. Zero-init + @P LDG keeps
    // 5 independent float4 loads in flight before any FADD consumes one.
#pragma unroll
    for (int w = 0; w < 2; w++) {
        float4 v[5];
#pragma unroll
        for (int j = 0; j < 5; j++) {
            const int n = w * 5 + j;
            v[j] = make_float4(0.f, 0.f, 0.f, 0.f);
            if (m[n]) {
                v[j] = *reinterpret_cast<const float4*>(
                    table + (size_t)k[n] * EMB + lane * 4);
            }
        }
#pragma unroll
        for (int j = 0; j < 5; j++) {
            acc.x += v[j].x; acc.y += v[j].y;
            acc.z += v[j].z; acc.w += v[j].w;
        }
    }

    const float inv = 1.0f / (float)(cnt > 0 ? cnt : 1);
    float4 r;
    r.x = acc.x * inv;
    r.y = acc.y * inv;
    r.z = acc.z * inv;
    r.w = acc.w * inv;

    // Streaming store: evict-first in L2, protect the table's resident set.
    __stcs(reinterpret_cast<float4*>(out + (size_t)pair * EMB + lane * 4), r);
}

extern "C" void kernel_launch(void* const* d_in, const int* in_sizes, int n_in,
                              void* d_out, int out_size)
{
    const int*   keys  = (const int*)d_in[0];
    const int*   mask  = (const int*)d_in[1];
    const float* table = (const float*)d_in[2];
    float*       out   = (float*)d_out;

    const int total_threads = PAIRS * LANES_PER_PAIR;
    const int blocks = (total_threads + THREADS - 1) / THREADS;
    emb_lookup_kernel<<<blocks, THREADS>>>(keys, mask, table, out);
}

// round 17
// speedup vs baseline: 1.1936x; 1.0266x over previous
#include <cuda_runtime.h>
#include <cuda_bf16.h>

// Problem shape (fixed by reference)
#define VOCAB   1000000
#define EMB     64
#define BATCH   4096
#define SLOTS   26
#define MAX_NNZ 10

static constexpr int PAIRS = BATCH * SLOTS;          // 106,496 (b,s) pairs
static constexpr int LANES_PER_PAIR = 16;            // 16 threads x float4 = 64 floats
static constexpr int THREADS = 256;

// CONVERGED FINAL — R9 shape, verified twice (R9: 31.46us, R16: 32.06us;
// kernel 29.8/29.3us). At the roofline for this access pattern:
//
//   traffic check: 29.3us x 5176 GB/s ~= 152MB
//                  = 121MB unique rows + 27MB out + 5MB keys  (exact match)
//   -> L2 already dedups ALL key reuse (1.06M gathers -> 472K unique rows
//      fetched once). No removable traffic remains.
//   -> Remaining gap to 8TB/s spec is DRAM page-locality of a random 256B
//      granule stream; only a per-launch key sort could fix it, and that
//      costs more than it recovers.
//
// Rejected by measurement: deep-MLP/low-occ (R11), L2 evict_last (R13, warm
// thrash), 256-bit v8 loads (R14, lost parallelism), 512-thr blocks +
// bitmask repack (R15, occupancy broke).
//
// Shape: one (batch,slot) pair per 16-thread group, one float4 per lane ->
// every row gather is a fully coalesced 256B read (one LDG.E.128 warp
// instruction covers two pairs' rows). Masked rows never loaded. Keys/mask
// preloaded as int2; 2 waves x 5 predicated gathers keep 5 independent
// LDG.128s in flight per thread at the 32-reg/81%-occ sweet spot. Output via
// streaming stores.
__global__ __launch_bounds__(THREADS)
void emb_lookup_kernel(const int* __restrict__ keys,
                       const int* __restrict__ mask,
                       const float* __restrict__ table,
                       float* __restrict__ out)
{
    const int gid  = blockIdx.x * THREADS + threadIdx.x;
    const int pair = gid >> 4;          // (b*SLOTS + s)
    const int lane = gid & 15;          // which float4 of the 64-dim vector
    if (pair >= PAIRS) return;

    const int base = pair * MAX_NNZ;

    // Vectorized key/mask preload: 5x int2 each (40B per pair, 8B aligned).
    const int2* kp = reinterpret_cast<const int2*>(keys + base);
    const int2* mp = reinterpret_cast<const int2*>(mask + base);
    int  k[MAX_NNZ];
    bool m[MAX_NNZ];
#pragma unroll
    for (int j = 0; j < 5; j++) {
        const int2 kk = kp[j];
        const int2 mm = mp[j];
        k[2*j]   = kk.x;  k[2*j+1] = kk.y;
        m[2*j]   = (mm.x != 0);          // works for int32 0/1 AND f32 0.0/1.0 bits
        m[2*j+1] = (mm.y != 0);
    }

    int cnt = 0;
#pragma unroll
    for (int n = 0; n < MAX_NNZ; n++) cnt += m[n] ? 1 : 0;

    float4 acc = make_float4(0.f, 0.f, 0.f, 0.f);

    // Two waves of 5 batched, predicated gathers. Zero-init + @P LDG keeps
    // 5 independent float4 loads in flight before any FADD consumes one.
#pragma unroll
    for (int w = 0; w < 2; w++) {
        float4 v[5];
#pragma unroll
        for (int j = 0; j < 5; j++) {
            const int n = w * 5 + j;
            v[j] = make_float4(0.f, 0.f, 0.f, 0.f);
            if (m[n]) {
                v[j] = *reinterpret_cast<const float4*>(
                    table + (size_t)k[n] * EMB + lane * 4);
            }
        }
#pragma unroll
        for (int j = 0; j < 5; j++) {
            acc.x += v[j].x; acc.y += v[j].y;
            acc.z += v[j].z; acc.w += v[j].w;
        }
    }

    const float inv = 1.0f / (float)(cnt > 0 ? cnt : 1);
    float4 r;
    r.x = acc.x * inv;
    r.y = acc.y * inv;
    r.z = acc.z * inv;
    r.w = acc.w * inv;

    // Streaming store: evict-first in L2, protect the table's resident set.
    __stcs(reinterpret_cast<float4*>(out + (size_t)pair * EMB + lane * 4), r);
}

extern "C" void kernel_launch(void* const* d_in, const int* in_sizes, int n_in,
                              void* d_out, int out_size)
{
    const int*   keys  = (const int*)d_in[0];
    const int*   mask  = (const int*)d_in[1];
    const float* table = (const float*)d_in[2];
    float*       out   = (float*)d_out;

    const int total_threads = PAIRS * LANES_PER_PAIR;
    const int blocks = (total_threads + THREADS - 1) / THREADS;
    emb_lookup_kernel<<<blocks, THREADS>>>(keys, mask, table, out);
}